// round 10
// baseline (speedup 1.0000x reference)
#include <cuda_runtime.h>
#include <cuda_bf16.h>
#include <math.h>
#include <stdint.h>

// Problem constants
#define B_DIM     32
#define S_DIM     2048
#define ROWS      65536
#define F_DIM     8
#define D_NODE    128
#define D_K       192
#define D_OUT     64
#define N_BT      64
#define N_ET      50
#define N_EQ      100

#define OFF_BT    192
#define OFF_POP   224
#define OFF_ET    240
#define OFF_EQ    272

#define THREADS   256
#define TILE_M    128
#define NKS       12                  // 192 / 16 k per mma step

// bf16 row stride: 192 data + 8 pad = 200 elems = 400 B (16B-aligned; banks
// advance 4/row -> ldmatrix 8-row phases conflict-free)
#define WSTRIDE   200

// smem layout (bytes)
#define SM_W_HI   0
#define SM_W_LO   25600
#define SM_A_HI   51200               // 128 rows * 400 B
#define SM_A_LO   102400
#define SM_CNT    153600              // 128 floats
#define SMEM_BYTES 154112
#define SM_DT     SM_A_HI             // Dt[128][72] f32 = 36864 B, fits in A_hi
#define DT_STRIDE 72

// Scratch (no cudaMalloc allowed)
__device__ uint4 g_Wbf[2 * 1600];     // Wt hi then lo, [64][200] bf16 each
__device__ float g_btype_proj[N_BT * D_OUT];
__device__ float g_etype_proj[N_ET * D_OUT];
__device__ float g_equip_proj[N_EQ * D_OUT];
__device__ float g_pv0[D_OUT];
__device__ float g_pv1[D_OUT];

// ---------------------------------------------------------------------------
// helpers
// ---------------------------------------------------------------------------
__device__ __forceinline__ uint32_t smem_u32(const void* p) {
    uint32_t a;
    asm("{ .reg .u64 t; cvta.to.shared.u64 t, %1; cvt.u32.u64 %0, t; }"
        : "=r"(a) : "l"(p));
    return a;
}
__device__ __forceinline__ uint32_t prmt_hi(float x0, float x1) {
    uint32_t d;
    asm("prmt.b32 %0, %1, %2, 0x7632;"
        : "=r"(d) : "r"(__float_as_uint(x0)), "r"(__float_as_uint(x1)));
    return d;
}
__device__ __forceinline__ float trunc_bf16(float x) {
    return __uint_as_float(__float_as_uint(x) & 0xFFFF0000u);
}
__device__ __forceinline__ uint32_t pack_bf16(float x0, float x1) {
    uint32_t d;
    asm("cvt.rn.bf16x2.f32 %0, %1, %2;" : "=r"(d) : "f"(x1), "f"(x0));
    return d;
}
__device__ __forceinline__ void ldsm_x4(uint32_t addr, uint32_t* r) {
    asm volatile("ldmatrix.sync.aligned.m8n8.x4.shared.b16 {%0,%1,%2,%3}, [%4];"
                 : "=r"(r[0]), "=r"(r[1]), "=r"(r[2]), "=r"(r[3]) : "r"(addr));
}
__device__ __forceinline__ void mma_bf16(float* d, const uint32_t* a,
                                         uint32_t b0, uint32_t b1) {
    asm volatile(
        "mma.sync.aligned.m16n8k16.row.col.f32.bf16.bf16.f32 "
        "{%0,%1,%2,%3}, {%4,%5,%6,%7}, {%8,%9}, {%0,%1,%2,%3};"
        : "+f"(d[0]), "+f"(d[1]), "+f"(d[2]), "+f"(d[3])
        : "r"(a[0]), "r"(a[1]), "r"(a[2]), "r"(a[3]), "r"(b0), "r"(b1));
}

// ---------------------------------------------------------------------------
// Precompute (unchanged from R9)
// ---------------------------------------------------------------------------
__global__ void precompute_tables(const float* __restrict__ btype_table,
                                  const float* __restrict__ etype_table,
                                  const float* __restrict__ equip_table,
                                  const float* __restrict__ pop_w,
                                  const float* __restrict__ pop_b,
                                  const float* __restrict__ proj_w,
                                  const float* __restrict__ proj_b) {
    int j = threadIdx.x;
    int n = blockIdx.x;
    if (n < N_BT) {
        float a = 0.f;
        #pragma unroll
        for (int d = 0; d < 32; ++d)
            a += btype_table[n * 32 + d] * proj_w[(OFF_BT + d) * D_OUT + j];
        g_btype_proj[n * D_OUT + j] = a;
    } else if (n < N_BT + N_ET) {
        int m = n - N_BT;
        float a = 0.f;
        #pragma unroll
        for (int d = 0; d < 32; ++d)
            a += etype_table[m * 32 + d] * proj_w[(OFF_ET + d) * D_OUT + j];
        g_etype_proj[m * D_OUT + j] = a;
    } else if (n < N_BT + N_ET + N_EQ) {
        int m = n - N_BT - N_ET;
        float a = 0.f;
        #pragma unroll
        for (int d = 0; d < 32; ++d)
            a += equip_table[m * 32 + d] * proj_w[(OFF_EQ + d) * D_OUT + j];
        g_equip_proj[m * D_OUT + j] = a;
    } else if (n == N_BT + N_ET + N_EQ) {
        float a0 = 0.f, a1 = 0.f;
        #pragma unroll
        for (int d = 0; d < 16; ++d) {
            float w = proj_w[(OFF_POP + d) * D_OUT + j];
            a0 += pop_w[d] * w;
            a1 += pop_b[d] * w;
        }
        g_pv0[j] = a0;
        g_pv1[j] = a1 + proj_b[j];
    } else {
        int nc = n - (N_BT + N_ET + N_EQ + 1);   // output col 0..63
        unsigned short* hi = (unsigned short*)g_Wbf;
        unsigned short* lo = hi + 64 * WSTRIDE;
        #pragma unroll
        for (int i = 0; i < 3; ++i) {
            int k = j + 64 * i;
            float x  = proj_w[k * D_OUT + nc];
            float xh = trunc_bf16(x);
            hi[nc * WSTRIDE + k] = (unsigned short)(__float_as_uint(x) >> 16);
            lo[nc * WSTRIDE + k] =
                __bfloat16_as_ushort(__float2bfloat16(x - xh));
        }
    }
}

// ---------------------------------------------------------------------------
// Main kernel: TILE 128 rows, 256 threads / 8 warps, 1 CTA/SM.
// Warp w: mt2 = w>>1 (32 rows = 2 m-tiles), nh = w&1 (32 cols).
// Per ks: 8 ldsm / 24 HMMA (B frags amortized over 2 m-tiles).
// ---------------------------------------------------------------------------
__global__ void __launch_bounds__(THREADS, 1)
combined_embedding_kernel(const int*   __restrict__ nbr_ids,
                          const float* __restrict__ time_feat,
                          const int*   __restrict__ bt_ids,
                          const float* __restrict__ counts,
                          const float* __restrict__ population,
                          const int*   __restrict__ et_ids,
                          const int*   __restrict__ eq_ids,
                          const float* __restrict__ node2vec,
                          const float* __restrict__ t2v_w,
                          const float* __restrict__ t2v_b,
                          float*       __restrict__ out) {
    extern __shared__ char smem[];
    const uint32_t sb = smem_u32(smem);
    float* counts_s = (float*)(smem + SM_CNT);

    const int tid  = threadIdx.x;
    const int lane = tid & 31;
    const int warp = tid >> 5;
    const int ctabase = blockIdx.x * TILE_M;

    // --- stage Wt hi/lo (once per 128 rows now) ---
    {
        uint4* dst = (uint4*)smem;
        #pragma unroll
        for (int i = 0; i < 13; ++i) {
            int idx = i * THREADS + tid;
            if (idx < 3200) dst[idx] = g_Wbf[idx];
        }
    }

    // --- counts_sum for this CTA's 128 s-values (2 threads per s) ---
    {
        int sl = tid >> 1, q = tid & 1;
        int sg = (ctabase & (S_DIM - 1)) + sl;
        float p = 0.f;
        #pragma unroll
        for (int i = 0; i < 16; ++i) p += counts[(q * 16 + i) * S_DIM + sg];
        p += __shfl_xor_sync(0xffffffffu, p, 1);
        if (q == 0) counts_s[sl] = p;
    }

    // --- Phase 1: stage A (hi/lo bf16, stride 400B), 2 row-groups ---
    #pragma unroll
    for (int r2 = 0; r2 < 2; ++r2) {
        int rt = (tid >> 2) + 64 * r2;
        int q  = tid & 3;
        int row = ctabase + rt;
        int nid = nbr_ids[row];
        const float4* src = (const float4*)(node2vec + (size_t)nid * D_NODE) + q * 8;
        char* ah = smem + SM_A_HI + rt * 400 + q * 64;
        char* al = smem + SM_A_LO + rt * 400 + q * 64;
        #pragma unroll
        for (int i = 0; i < 4; ++i) {
            float4 v0 = src[2 * i];
            float4 v1 = src[2 * i + 1];
            uint4 h = make_uint4(prmt_hi(v0.x, v0.y), prmt_hi(v0.z, v0.w),
                                 prmt_hi(v1.x, v1.y), prmt_hi(v1.z, v1.w));
            uint4 l = make_uint4(
                pack_bf16(v0.x - trunc_bf16(v0.x), v0.y - trunc_bf16(v0.y)),
                pack_bf16(v0.z - trunc_bf16(v0.z), v0.w - trunc_bf16(v0.w)),
                pack_bf16(v1.x - trunc_bf16(v1.x), v1.y - trunc_bf16(v1.y)),
                pack_bf16(v1.z - trunc_bf16(v1.z), v1.w - trunc_bf16(v1.w)));
            *(uint4*)(ah + i * 16) = h;
            *(uint4*)(al + i * 16) = l;
        }

        // t2v: 16 values kk = q*16 .. q*16+15  (k = 128+kk)
        float xa = time_feat[row * F_DIM + 2 * q];
        float xb = time_feat[row * F_DIM + 2 * q + 1];
        float v[16];
        #pragma unroll
        for (int i = 0; i < 16; ++i) {
            int kk = q * 16 + i;
            float x = (i < 8) ? xa : xb;
            float a = fmaf(x, t2v_w[kk], t2v_b[kk]);
            v[i] = (kk & 7) ? __sinf(a) : a;
        }
        char* th = smem + SM_A_HI + rt * 400 + 256 + q * 32;
        char* tl = smem + SM_A_LO + rt * 400 + 256 + q * 32;
        #pragma unroll
        for (int h = 0; h < 2; ++h) {
            uint4 hp = make_uint4(prmt_hi(v[8*h+0], v[8*h+1]), prmt_hi(v[8*h+2], v[8*h+3]),
                                  prmt_hi(v[8*h+4], v[8*h+5]), prmt_hi(v[8*h+6], v[8*h+7]));
            uint4 lp = make_uint4(
                pack_bf16(v[8*h+0]-trunc_bf16(v[8*h+0]), v[8*h+1]-trunc_bf16(v[8*h+1])),
                pack_bf16(v[8*h+2]-trunc_bf16(v[8*h+2]), v[8*h+3]-trunc_bf16(v[8*h+3])),
                pack_bf16(v[8*h+4]-trunc_bf16(v[8*h+4]), v[8*h+5]-trunc_bf16(v[8*h+5])),
                pack_bf16(v[8*h+6]-trunc_bf16(v[8*h+6]), v[8*h+7]-trunc_bf16(v[8*h+7])));
            *(uint4*)(th + h * 16) = hp;
            *(uint4*)(tl + h * 16) = lp;
        }
    }
    __syncthreads();

    // --- Phase 2: mma.sync, 3-pass split bf16, 32x32 per warp ---
    const int mt2 = warp >> 1;       // 0..3 -> rows 32*mt2 .. +31
    const int nh  = warp & 1;

    uint32_t aAddr = sb + SM_A_HI + (mt2 * 32 + (lane & 15)) * 400 + (lane >> 4) * 16;
    uint32_t nb = nh * 32 + (lane & 7) + ((lane >> 4) << 3);
    uint32_t bAddr = sb + SM_W_HI + nb * 400 + ((lane >> 3) & 1) * 16;

    float D[2][4][4];
    #pragma unroll
    for (int mi = 0; mi < 2; ++mi)
        #pragma unroll
        for (int nt = 0; nt < 4; ++nt)
            #pragma unroll
            for (int i = 0; i < 4; ++i) D[mi][nt][i] = 0.f;

    #pragma unroll
    for (int ks = 0; ks < NKS; ++ks) {
        uint32_t kb = ks * 32;
        uint32_t Ahi0[4], Ahi1[4], Alo0[4], Alo1[4], Bhi[8], Blo[8];
        ldsm_x4(aAddr + kb,         Ahi0);
        ldsm_x4(aAddr + 6400 + kb,  Ahi1);          // +16 rows * 400B
        ldsm_x4(aAddr + 51200 + kb, Alo0);          // A_LO offset
        ldsm_x4(aAddr + 57600 + kb, Alo1);
        ldsm_x4(bAddr + kb,         Bhi);           // nt 0,1
        ldsm_x4(bAddr + 6400 + kb,  Bhi + 4);       // nt 2,3
        ldsm_x4(bAddr + 25600 + kb, Blo);
        ldsm_x4(bAddr + 32000 + kb, Blo + 4);
        #pragma unroll
        for (int nt = 0; nt < 4; ++nt) {
            mma_bf16(D[0][nt], Ahi0, Bhi[2 * nt], Bhi[2 * nt + 1]);
            mma_bf16(D[0][nt], Ahi0, Blo[2 * nt], Blo[2 * nt + 1]);
            mma_bf16(D[0][nt], Alo0, Bhi[2 * nt], Bhi[2 * nt + 1]);
            mma_bf16(D[1][nt], Ahi1, Bhi[2 * nt], Bhi[2 * nt + 1]);
            mma_bf16(D[1][nt], Ahi1, Blo[2 * nt], Blo[2 * nt + 1]);
            mma_bf16(D[1][nt], Alo1, Bhi[2 * nt], Bhi[2 * nt + 1]);
        }
    }
    __syncthreads();     // all ldmatrix reads done before Dt overwrites A_hi

    // --- Dt transpose: D frags -> Dt[128][72] f32 ---
    {
        float* Dt = (float*)(smem + SM_DT);
        int r0 = mt2 * 32 + (lane >> 2);
        int c0 = nh * 32 + (lane & 3) * 2;
        #pragma unroll
        for (int mi = 0; mi < 2; ++mi) {
            int r = r0 + mi * 16;
            #pragma unroll
            for (int nt = 0; nt < 4; ++nt) {
                int c = c0 + nt * 8;
                *(float2*)(Dt + r * DT_STRIDE + c) =
                    make_float2(D[mi][nt][0], D[mi][nt][1]);
                *(float2*)(Dt + (r + 8) * DT_STRIDE + c) =
                    make_float2(D[mi][nt][2], D[mi][nt][3]);
            }
        }
    }
    __syncthreads();

    // --- Epilogue: thread = (rgrp = t>>4 of 8 rows, jq = t&15) ---
    {
        const float* Dt = (const float*)(smem + SM_DT);
        int jq   = tid & 15;
        int rgrp = tid >> 4;
        #pragma unroll
        for (int rr = 0; rr < 8; ++rr) {
            int rl  = rgrp * 8 + rr;
            int row = ctabase + rl;
            float4 acc = *(const float4*)(Dt + rl * DT_STRIDE + 4 * jq);

            float c  = counts_s[rl];
            float pp = population[row];
            int bt = bt_ids[row], et = et_ids[row], eq = eq_ids[row];

            float4 tb = *(const float4*)(g_btype_proj + bt * D_OUT + 4 * jq);
            float4 te = *(const float4*)(g_etype_proj + et * D_OUT + 4 * jq);
            float4 tq = *(const float4*)(g_equip_proj + eq * D_OUT + 4 * jq);
            float4 v0 = *(const float4*)(g_pv0 + 4 * jq);
            float4 v1 = *(const float4*)(g_pv1 + 4 * jq);

            acc.x += c * tb.x + te.x + tq.x + pp * v0.x + v1.x;
            acc.y += c * tb.y + te.y + tq.y + pp * v0.y + v1.y;
            acc.z += c * tb.z + te.z + tq.z + pp * v0.z + v1.z;
            acc.w += c * tb.w + te.w + tq.w + pp * v0.w + v1.w;

            *(float4*)(out + (size_t)row * D_OUT + 4 * jq) = acc;
        }
    }
}

// ---------------------------------------------------------------------------
extern "C" void kernel_launch(void* const* d_in, const int* in_sizes, int n_in,
                              void* d_out, int out_size) {
    const int*   nbr     = (const int*)  d_in[0];
    const float* tfeat   = (const float*)d_in[1];
    const int*   bt      = (const int*)  d_in[2];
    const float* counts  = (const float*)d_in[3];
    const float* pop     = (const float*)d_in[4];
    const int*   et      = (const int*)  d_in[5];
    const int*   eq      = (const int*)  d_in[6];
    const float* n2v     = (const float*)d_in[7];
    const float* t2vw    = (const float*)d_in[8];
    const float* t2vb    = (const float*)d_in[9];
    const float* btt     = (const float*)d_in[10];
    const float* popw    = (const float*)d_in[11];
    const float* popb    = (const float*)d_in[12];
    const float* ett     = (const float*)d_in[13];
    const float* eqt     = (const float*)d_in[14];
    const float* pw      = (const float*)d_in[15];
    const float* pb      = (const float*)d_in[16];
    float*       out     = (float*)d_out;

    precompute_tables<<<N_BT + N_ET + N_EQ + 1 + 64, 64>>>(
        btt, ett, eqt, popw, popb, pw, pb);

    cudaFuncSetAttribute(combined_embedding_kernel,
                         cudaFuncAttributeMaxDynamicSharedMemorySize, SMEM_BYTES);
    combined_embedding_kernel<<<ROWS / TILE_M, THREADS, SMEM_BYTES>>>(
        nbr, tfeat, bt, counts, pop, et, eq, n2v, t2vw, t2vb, out);
}